// round 16
// baseline (speedup 1.0000x reference)
#include <cuda_runtime.h>
#include <cuda_bf16.h>
#include <cstdint>

#define DD 1024
#define MM 512
#define CC 256
#define BB 8192
#define NS_ITERS 11
#define NS_FULL  3          // last NS_FULL iterations use full split-2

typedef __nv_bfloat16 bf16;

// ---------------- fp32 scratch ----------------------------------------------
__device__ __align__(16) float g_sp[DD * BB];        // 32 MB
__device__ __align__(16) float g_fs[DD * DD];
__device__ __align__(16) float g_cp[DD * DD];
__device__ __align__(16) float g_innov[MM * BB];     // 16 MB
__device__ __align__(16) float g_hp[MM * DD];
__device__ __align__(16) float g_S[MM * MM];
__device__ __align__(16) float g_X[MM * MM];
__device__ __align__(16) float g_X2[MM * MM];
__device__ __align__(16) float g_T[MM * MM];
__device__ __align__(16) float g_pht[DD * MM];
__device__ __align__(16) float g_K[DD * MM];
__device__ __align__(16) float g_norms[2];
// ---------------- bf16 plane scratch ----------------------------------------
__device__ __align__(16) bf16 g_Fh[DD*DD],   g_Fl[DD*DD];
__device__ __align__(16) bf16 g_Hh[MM*DD],   g_Hl[MM*DD];
__device__ __align__(16) bf16 g_Bch[DD*CC],  g_Bcl[DD*CC];
__device__ __align__(16) bf16 g_BTh[BB*DD],  g_BTl[BB*DD];
__device__ __align__(16) bf16 g_CTh[DD*DD],  g_CTl[DD*DD];
__device__ __align__(16) bf16 g_CtlTh[BB*CC],g_CtlTl[BB*CC];
__device__ __align__(16) bf16 g_FSh[DD*DD],  g_FSl[DD*DD];
__device__ __align__(16) bf16 g_CPh[DD*DD],  g_CPl[DD*DD];
__device__ __align__(16) bf16 g_CPTh[DD*DD], g_CPTl[DD*DD];
__device__ __align__(16) bf16 g_HPh[MM*DD],  g_HPl[MM*DD];
__device__ __align__(16) bf16 g_HPTh[DD*MM], g_HPTl[DD*MM];
__device__ __align__(16) bf16 g_Sh[MM*MM],   g_Sl[MM*MM];
__device__ __align__(16) bf16 g_PHh[DD*MM],  g_PHl[DD*MM];
__device__ __align__(16) bf16 g_XAh[MM*MM],  g_XAl[MM*MM];
__device__ __align__(16) bf16 g_XBh[MM*MM],  g_XBl[MM*MM];
__device__ __align__(16) bf16 g_XTh[MM*MM],  g_XTl[MM*MM];
__device__ __align__(16) bf16 g_TTh[MM*MM],  g_TTl[MM*MM];
__device__ __align__(16) bf16 g_Kh[DD*MM],   g_Kl[DD*MM];

// ---------------- split helpers ---------------------------------------------
__device__ __forceinline__ void hl(float v, bf16& h, bf16& l) {
    h = __float2bfloat16_rn(v);
    l = __float2bfloat16_rn(v - __bfloat162float(h));
}

__global__ void split_kernel(const float4* __restrict__ in,
                             bf16* __restrict__ hi, bf16* __restrict__ lo, int n4)
{
    int i = blockIdx.x * blockDim.x + threadIdx.x;
    if (i >= n4) return;
    float4 v = in[i];
    bf16 h0,h1,h2,h3,l0,l1,l2,l3;
    hl(v.x,h0,l0); hl(v.y,h1,l1); hl(v.z,h2,l2); hl(v.w,h3,l3);
    ((__nv_bfloat162*)hi)[2*i+0] = __nv_bfloat162(h0,h1);
    ((__nv_bfloat162*)hi)[2*i+1] = __nv_bfloat162(h2,h3);
    ((__nv_bfloat162*)lo)[2*i+0] = __nv_bfloat162(l0,l1);
    ((__nv_bfloat162*)lo)[2*i+1] = __nv_bfloat162(l2,l3);
}

// transpose-split: src [R,C] -> planes [C,R]
__global__ void splitT_kernel(const float* __restrict__ in,
                              bf16* __restrict__ hi, bf16* __restrict__ lo,
                              int R, int C)
{
    __shared__ float t[32][33];
    const int r0 = blockIdx.y * 32, c0 = blockIdx.x * 32;
    const int tx = threadIdx.x, ty = threadIdx.y;  // 32 x 8
#pragma unroll
    for (int i = 0; i < 32; i += 8)
        t[ty + i][tx] = in[(size_t)(r0 + ty + i) * C + c0 + tx];
    __syncthreads();
#pragma unroll
    for (int i = 0; i < 32; i += 8) {
        bf16 h, l; hl(t[tx][ty + i], h, l);
        size_t o = (size_t)(c0 + ty + i) * R + r0 + tx;
        hi[o] = h; lo[o] = l;
    }
}

// ======================= cp.async helpers ===================================
__device__ __forceinline__ uint32_t smem_u32(const void* p) {
    return (uint32_t)__cvta_generic_to_shared(p);
}
__device__ __forceinline__ void cp16(uint32_t dst, const void* src) {
    asm volatile("cp.async.cg.shared.global [%0], [%1], 16;"
                 :: "r"(dst), "l"(src));
}
__device__ __forceinline__ void cp_commit() {
    asm volatile("cp.async.commit_group;");
}
__device__ __forceinline__ void cp_wait0() {
    asm volatile("cp.async.wait_group 0;");
}

// ======================= double-buffered plane GEMM =========================
// C = alpha * A@B + beta*Cin via split-2 bf16 (lo*lo dropped).
// FULL=false: hi-plane-only. Global->smem via cp.async (no register staging).
__device__ __forceinline__ void mma16816(float c[4], const uint32_t a[4],
                                         uint32_t b0, uint32_t b1) {
    asm volatile("mma.sync.aligned.m16n8k16.row.col.f32.bf16.bf16.f32 "
                 "{%0,%1,%2,%3}, {%4,%5,%6,%7}, {%8,%9}, {%0,%1,%2,%3};"
                 : "+f"(c[0]), "+f"(c[1]), "+f"(c[2]), "+f"(c[3])
                 : "r"(a[0]), "r"(a[1]), "r"(a[2]), "r"(a[3]), "r"(b0), "r"(b1));
}
__device__ __forceinline__ void store_hl2(bf16* hi, bf16* lo, size_t off, float2 v) {
    bf16 h0,l0,h1,l1; hl(v.x,h0,l0); hl(v.y,h1,l1);
    *(__nv_bfloat162*)(hi + off) = __nv_bfloat162(h0,h1);
    *(__nv_bfloat162*)(lo + off) = __nv_bfloat162(l0,l1);
}
__device__ __forceinline__ void store_hlT(bf16* th, bf16* tl, int Mdim,
                                          int row, int col, float2 v) {
    bf16 h, l;
    hl(v.x, h, l);
    th[(size_t)col * Mdim + row] = h; tl[(size_t)col * Mdim + row] = l;
    hl(v.y, h, l);
    th[(size_t)(col + 1) * Mdim + row] = h; tl[(size_t)(col + 1) * Mdim + row] = l;
}

template <int BM, bool FULL>
__global__ __launch_bounds__(2 * BM)
void pgemm(int M, int N, int K,
           const bf16* __restrict__ Ah, const bf16* __restrict__ Al,
           const bf16* __restrict__ Bh, const bf16* __restrict__ Bl,
           const float* __restrict__ Cin, float* __restrict__ Cout,
           float alpha, float beta,
           bf16* __restrict__ Ph, bf16* __restrict__ Pl,
           bf16* __restrict__ PTh, bf16* __restrict__ PTl)
{
    constexpr int SA = 24;
    constexpr int NG = BM / 16;
    __shared__ alignas(16) bf16 sAh[2][BM * SA];
    __shared__ alignas(16) bf16 sBh[2][BM * SA];
    __shared__ alignas(16) bf16 sAl[FULL ? 2 : 1][BM * SA];
    __shared__ alignas(16) bf16 sBl[FULL ? 2 : 1][BM * SA];

    const int tid = threadIdx.x;
    const int wid = tid / 32, lane = tid % 32;
    const int warpM = wid / 2, warpN = wid % 2;
    const int g = lane >> 2, t = lane & 3;
    const int bm = blockIdx.y * BM, bn = blockIdx.x * BM;

    const int arow = tid >> 1, acol = (tid & 1) * 8;
    const int soff = arow * SA + acol;

    // async global->smem for one K-step into stage s
    auto ldcp = [&](int k0, int s) {
        cp16(smem_u32(&sAh[s][soff]), Ah + (size_t)(bm + arow) * K + k0 + acol);
        cp16(smem_u32(&sBh[s][soff]), Bh + (size_t)(bn + arow) * K + k0 + acol);
        if (FULL) {
            cp16(smem_u32(&sAl[s][soff]), Al + (size_t)(bm + arow) * K + k0 + acol);
            cp16(smem_u32(&sBl[s][soff]), Bl + (size_t)(bn + arow) * K + k0 + acol);
        }
    };

    float acc[2][NG][4];
#pragma unroll
    for (int mt = 0; mt < 2; mt++)
#pragma unroll
        for (int nt = 0; nt < NG; nt++)
#pragma unroll
            for (int q = 0; q < 4; q++) acc[mt][nt][q] = 0.f;

    ldcp(0, 0); cp_commit();
    int s = 0;
    for (int k0 = 0; k0 < K; k0 += 16) {
        const bool hasNext = (k0 + 16 < K);
        cp_wait0();          // this thread's pending copies done
        __syncthreads();     // all threads' copies visible; prior compute done
        if (hasNext) { ldcp(k0 + 16, s ^ 1); cp_commit(); }

        uint32_t ah[2][4], al[2][4];
#pragma unroll
        for (int mt = 0; mt < 2; mt++) {
            const int r = warpM * 32 + mt * 16;
            ah[mt][0] = *(const uint32_t*)&sAh[s][(r + g) * SA + 2 * t];
            ah[mt][1] = *(const uint32_t*)&sAh[s][(r + g + 8) * SA + 2 * t];
            ah[mt][2] = *(const uint32_t*)&sAh[s][(r + g) * SA + 2 * t + 8];
            ah[mt][3] = *(const uint32_t*)&sAh[s][(r + g + 8) * SA + 2 * t + 8];
            if (FULL) {
                al[mt][0] = *(const uint32_t*)&sAl[s][(r + g) * SA + 2 * t];
                al[mt][1] = *(const uint32_t*)&sAl[s][(r + g + 8) * SA + 2 * t];
                al[mt][2] = *(const uint32_t*)&sAl[s][(r + g) * SA + 2 * t + 8];
                al[mt][3] = *(const uint32_t*)&sAl[s][(r + g + 8) * SA + 2 * t + 8];
            }
        }
#pragma unroll
        for (int ng = 0; ng < NG; ng++) {
            const int n = warpN * (BM / 2) + ng * 8 + g;
            uint32_t bh0 = *(const uint32_t*)&sBh[s][n * SA + 2 * t];
            uint32_t bh1 = *(const uint32_t*)&sBh[s][n * SA + 2 * t + 8];
            if (FULL) {
                uint32_t bl0 = *(const uint32_t*)&sBl[s][n * SA + 2 * t];
                uint32_t bl1 = *(const uint32_t*)&sBl[s][n * SA + 2 * t + 8];
#pragma unroll
                for (int mt = 0; mt < 2; mt++) {
                    mma16816(acc[mt][ng], ah[mt], bh0, bh1);
                    mma16816(acc[mt][ng], ah[mt], bl0, bl1);
                    mma16816(acc[mt][ng], al[mt], bh0, bh1);
                }
            } else {
#pragma unroll
                for (int mt = 0; mt < 2; mt++)
                    mma16816(acc[mt][ng], ah[mt], bh0, bh1);
            }
        }
        s ^= 1;
    }

#pragma unroll
    for (int mt = 0; mt < 2; mt++) {
        const int rowb = bm + warpM * 32 + mt * 16;
#pragma unroll
        for (int nt = 0; nt < NG; nt++) {
            const int col = bn + warpN * (BM / 2) + nt * 8 + 2 * t;
            const int r0 = rowb + g, r1 = rowb + g + 8;
            float2 c01 = make_float2(alpha * acc[mt][nt][0], alpha * acc[mt][nt][1]);
            float2 c23 = make_float2(alpha * acc[mt][nt][2], alpha * acc[mt][nt][3]);
            if (beta != 0.f) {
                float2 p0 = *(const float2*)(Cin + (size_t)r0 * N + col);
                float2 p1 = *(const float2*)(Cin + (size_t)r1 * N + col);
                c01.x += beta * p0.x; c01.y += beta * p0.y;
                c23.x += beta * p1.x; c23.y += beta * p1.y;
            }
            *(float2*)(Cout + (size_t)r0 * N + col) = c01;
            *(float2*)(Cout + (size_t)r1 * N + col) = c23;
            if (Ph) {
                store_hl2(Ph, Pl, (size_t)r0 * N + col, c01);
                store_hl2(Ph, Pl, (size_t)r1 * N + col, c23);
            }
            if (PTh) {
                store_hlT(PTh, PTl, M, r0, col, c01);
                store_hlT(PTh, PTl, M, r1, col, c23);
            }
        }
    }
}

// ---------------- Newton-Schulz support -------------------------------------
__global__ void zero_norms_kernel(float* norms) {
    if (threadIdx.x < 2) norms[threadIdx.x] = 0.f;
}
__global__ void snorms_kernel(const float* __restrict__ S, float* norms) {
    __shared__ float sr[256], sc[256];
    const int i = blockIdx.x;
    float r = 0.f, c = 0.f;
    for (int j = threadIdx.x; j < MM; j += 256) {
        r += fabsf(S[(size_t)i * MM + j]);
        c += fabsf(S[(size_t)j * MM + i]);
    }
    sr[threadIdx.x] = r; sc[threadIdx.x] = c;
    __syncthreads();
    for (int o = 128; o > 0; o >>= 1) {
        if (threadIdx.x < o) {
            sr[threadIdx.x] += sr[threadIdx.x + o];
            sc[threadIdx.x] += sc[threadIdx.x + o];
        }
        __syncthreads();
    }
    if (threadIdx.x == 0) {
        atomicMax((int*)&norms[0], __float_as_int(sr[0]));
        atomicMax((int*)&norms[1], __float_as_int(sc[0]));
    }
}
__global__ void init_X_kernel(const float* __restrict__ S,
                              const float* __restrict__ norms,
                              float* __restrict__ X,
                              bf16* __restrict__ Xh, bf16* __restrict__ Xl,
                              bf16* __restrict__ XTh, bf16* __restrict__ XTl) {
    const float scale = 1.9f / (norms[0] * norms[1]);
    const int idx = blockIdx.x * blockDim.x + threadIdx.x;
    const int i = idx / MM, j = idx % MM;
    float v = S[(size_t)j * MM + i] * scale;
    X[idx] = v;
    bf16 h, l; hl(v, h, l);
    Xh[idx] = h; Xl[idx] = l;
    XTh[(size_t)j * MM + i] = h; XTl[(size_t)j * MM + i] = l;
}

// ---------------- host-side dispatch ----------------------------------------
#define SYM(p, s) cudaGetSymbolAddress((void**)&p, s)

static void pg(cudaStream_t st, int M, int N, int K,
               const bf16* Ah, const bf16* Al, const bf16* Bh, const bf16* Bl,
               const float* Cin, float* C, float alpha, float beta,
               bf16* Ph = nullptr, bf16* Pl = nullptr,
               bf16* PTh = nullptr, bf16* PTl = nullptr, bool full = true)
{
    if (N == BB) {
        dim3 grd(N / 128, M / 128);
        pgemm<128, true><<<grd, 256, 0, st>>>(M, N, K, Ah, Al, Bh, Bl, Cin, C,
                                              alpha, beta, Ph, Pl, PTh, PTl);
    } else {
        dim3 grd(N / 64, M / 64);
        if (full)
            pgemm<64, true><<<grd, 128, 0, st>>>(M, N, K, Ah, Al, Bh, Bl, Cin, C,
                                                 alpha, beta, Ph, Pl, PTh, PTl);
        else
            pgemm<64, false><<<grd, 128, 0, st>>>(M, N, K, Ah, Al, Bh, Bl, Cin, C,
                                                  alpha, beta, Ph, Pl, PTh, PTl);
    }
}
static void split(cudaStream_t st, const float* src, bf16* h, bf16* l, int n) {
    split_kernel<<<(n / 4 + 255) / 256, 256, 0, st>>>((const float4*)src, h, l, n / 4);
}
static void splitT(cudaStream_t st, const float* src, bf16* h, bf16* l, int R, int C) {
    splitT_kernel<<<dim3(C / 32, R / 32), dim3(32, 8), 0, st>>>(src, h, l, R, C);
}

extern "C" void kernel_launch(void* const* d_in, const int* in_sizes, int n_in,
                              void* d_out, int out_size)
{
    (void)in_sizes; (void)n_in; (void)out_size;
    const float* state     = (const float*)d_in[0];
    const float* state_cov = (const float*)d_in[1];
    const float* meas      = (const float*)d_in[2];
    const float* control   = (const float*)d_in[3];
    const float* F         = (const float*)d_in[4];
    const float* Q         = (const float*)d_in[5];
    const float* Bc        = (const float*)d_in[6];
    const float* H         = (const float*)d_in[7];
    const float* R         = (const float*)d_in[8];
    float* out_state = (float*)d_out;
    float* out_cov   = out_state + (size_t)DD * BB;

    float *sp,*fs,*cp,*innov,*hp,*S,*X,*X2,*T,*pht,*Kg,*norms;
    SYM(sp,g_sp); SYM(fs,g_fs); SYM(cp,g_cp); SYM(innov,g_innov); SYM(hp,g_hp);
    SYM(S,g_S); SYM(X,g_X); SYM(X2,g_X2); SYM(T,g_T); SYM(pht,g_pht);
    SYM(Kg,g_K); SYM(norms,g_norms);
    bf16 *Fh,*Fl,*Hh,*Hl,*Bch,*Bcl,*BTh,*BTl,*CTh,*CTl,*CtlTh,*CtlTl;
    bf16 *FSh,*FSl,*CPh,*CPl,*CPTh,*CPTl,*HPh,*HPl,*HPTh,*HPTl,*Sh,*Sl;
    bf16 *PHh,*PHl,*XAh,*XAl,*XBh,*XBl,*XTh,*XTl,*TTh,*TTl,*Kh,*Kl;
    SYM(Fh,g_Fh); SYM(Fl,g_Fl); SYM(Hh,g_Hh); SYM(Hl,g_Hl);
    SYM(Bch,g_Bch); SYM(Bcl,g_Bcl); SYM(BTh,g_BTh); SYM(BTl,g_BTl);
    SYM(CTh,g_CTh); SYM(CTl,g_CTl); SYM(CtlTh,g_CtlTh); SYM(CtlTl,g_CtlTl);
    SYM(FSh,g_FSh); SYM(FSl,g_FSl); SYM(CPh,g_CPh); SYM(CPl,g_CPl);
    SYM(CPTh,g_CPTh); SYM(CPTl,g_CPTl);
    SYM(HPh,g_HPh); SYM(HPl,g_HPl); SYM(HPTh,g_HPTh); SYM(HPTl,g_HPTl);
    SYM(Sh,g_Sh); SYM(Sl,g_Sl); SYM(PHh,g_PHh); SYM(PHl,g_PHl);
    SYM(XAh,g_XAh); SYM(XAl,g_XAl); SYM(XBh,g_XBh); SYM(XBl,g_XBl);
    SYM(XTh,g_XTh); SYM(XTl,g_XTl); SYM(TTh,g_TTh); SYM(TTl,g_TTl);
    SYM(Kh,g_Kh); SYM(Kl,g_Kl);

    cudaStream_t s2 = 0;
    cudaEvent_t evF = 0, evJ = 0;
    bool dual =
        (cudaStreamCreateWithFlags(&s2, cudaStreamNonBlocking) == cudaSuccess) &&
        (cudaEventCreateWithFlags(&evF, cudaEventDisableTiming) == cudaSuccess) &&
        (cudaEventCreateWithFlags(&evJ, cudaEventDisableTiming) == cudaSuccess);
    cudaStream_t sb = dual ? s2 : (cudaStream_t)0;
    cudaStream_t sm = 0;

    // ---- common splits (main) ----
    split(sm, F, Fh, Fl, DD * DD);
    split(sm, H, Hh, Hl, MM * DD);
    if (dual) { cudaEventRecord(evF, sm); cudaStreamWaitEvent(s2, evF, 0); }

    // ================= state chain (sb) =================
    split(sb, Bc, Bch, Bcl, DD * CC);
    splitT(sb, state, BTh, BTl, DD, BB);
    splitT(sb, control, CtlTh, CtlTl, CC, BB);
    pg(sb, DD, BB, DD, Fh, Fl, BTh, BTl, nullptr, sp, 1.f, 0.f);     // sp=F@state
    pg(sb, DD, BB, CC, Bch, Bcl, CtlTh, CtlTl, sp, sp, 1.f, 1.f);    // +Bc@ctl
    splitT(sb, sp, BTh, BTl, DD, BB);
    pg(sb, MM, BB, DD, Hh, Hl, BTh, BTl, meas, innov, -1.f, 1.f);    // innov
    splitT(sb, innov, BTh, BTl, MM, BB);                             // innov^T

    // ================= cov chain (sm) ===================
    splitT(sm, state_cov, CTh, CTl, DD, DD);
    pg(sm, DD, DD, DD, Fh, Fl, CTh, CTl, nullptr, fs, 1.f, 0.f,
       FSh, FSl);                                                    // fs
    pg(sm, DD, DD, DD, FSh, FSl, Fh, Fl, Q, cp, 1.f, 1.f,
       CPh, CPl, CPTh, CPTl);                                        // cp
    pg(sm, MM, DD, DD, Hh, Hl, CPTh, CPTl, nullptr, hp, 1.f, 0.f,
       HPh, HPl, HPTh, HPTl);                                        // hp
    pg(sm, MM, MM, DD, HPh, HPl, Hh, Hl, R, S, 1.f, 1.f, Sh, Sl);    // S
    pg(sm, DD, MM, DD, CPh, CPl, Hh, Hl, nullptr, pht, 1.f, 0.f,
       PHh, PHl);                                                    // pht

    zero_norms_kernel<<<1, 32, 0, sm>>>(norms);
    snorms_kernel<<<MM, 256, 0, sm>>>(S, norms);
    init_X_kernel<<<(MM * MM) / 256, 256, 0, sm>>>(S, norms, X, XAh, XAl,
                                                   XTh, XTl);
    float* cur = X;  float* nxt = X2;
    bf16 *curAh = XAh, *curAl = XAl, *nxtAh = XBh, *nxtAl = XBl;
    for (int it = 0; it < NS_ITERS; ++it) {
        const bool full = (it >= NS_ITERS - NS_FULL);
        pg(sm, MM, MM, MM, Sh, Sl, XTh, XTl, nullptr, T, 1.f, 0.f,
           nullptr, nullptr, TTh, TTl, full);                        // T=S@X
        pg(sm, MM, MM, MM, curAh, curAl, TTh, TTl, cur, nxt, -1.f, 2.f,
           nxtAh, nxtAl, XTh, XTl, full);                            // X'
        float* tf = cur; cur = nxt; nxt = tf;
        bf16* th = curAh; curAh = nxtAh; nxtAh = th;
        bf16* tl = curAl; curAl = nxtAl; nxtAl = tl;
    }
    pg(sm, DD, MM, MM, PHh, PHl, XTh, XTl, nullptr, Kg, 1.f, 0.f,
       Kh, Kl);                                                      // Kg

    // ================= join + outputs (sm) ==============
    if (dual) { cudaEventRecord(evJ, s2); cudaStreamWaitEvent(sm, evJ, 0); }
    pg(sm, DD, BB, MM, Kh, Kl, BTh, BTl, sp, out_state, 1.f, 1.f);   // state_n
    pg(sm, DD, DD, MM, Kh, Kl, HPTh, HPTl, cp, out_cov, -1.f, 1.f);  // cov_n
}

// round 17
// speedup vs baseline: 1.0353x; 1.0353x over previous
#include <cuda_runtime.h>
#include <cuda_bf16.h>
#include <cstdint>

#define DD 1024
#define MM 512
#define CC 256
#define BB 8192
#define NS_ITERS 9
#define NS_FULL  3          // last NS_FULL iterations use full split-2

typedef __nv_bfloat16 bf16;

// ---------------- fp32 scratch ----------------------------------------------
__device__ __align__(16) float g_sp[DD * BB];        // 32 MB
__device__ __align__(16) float g_fs[DD * DD];
__device__ __align__(16) float g_cp[DD * DD];
__device__ __align__(16) float g_innov[MM * BB];     // 16 MB
__device__ __align__(16) float g_hp[MM * DD];
__device__ __align__(16) float g_S[MM * MM];
__device__ __align__(16) float g_X[MM * MM];
__device__ __align__(16) float g_X2[MM * MM];
__device__ __align__(16) float g_T[MM * MM];
__device__ __align__(16) float g_pht[DD * MM];
__device__ __align__(16) float g_K[DD * MM];
__device__ __align__(16) float g_pv[4 * MM];         // power-iteration vectors
__device__ __align__(16) float g_norms[2];
// ---------------- bf16 plane scratch ----------------------------------------
__device__ __align__(16) bf16 g_Fh[DD*DD],   g_Fl[DD*DD];
__device__ __align__(16) bf16 g_Hh[MM*DD],   g_Hl[MM*DD];
__device__ __align__(16) bf16 g_Bch[DD*CC],  g_Bcl[DD*CC];
__device__ __align__(16) bf16 g_BTh[BB*DD],  g_BTl[BB*DD];
__device__ __align__(16) bf16 g_CTh[DD*DD],  g_CTl[DD*DD];
__device__ __align__(16) bf16 g_CtlTh[BB*CC],g_CtlTl[BB*CC];
__device__ __align__(16) bf16 g_FSh[DD*DD],  g_FSl[DD*DD];
__device__ __align__(16) bf16 g_CPh[DD*DD],  g_CPl[DD*DD];
__device__ __align__(16) bf16 g_CPTh[DD*DD], g_CPTl[DD*DD];
__device__ __align__(16) bf16 g_HPh[MM*DD],  g_HPl[MM*DD];
__device__ __align__(16) bf16 g_HPTh[DD*MM], g_HPTl[DD*MM];
__device__ __align__(16) bf16 g_Sh[MM*MM],   g_Sl[MM*MM];
__device__ __align__(16) bf16 g_PHh[DD*MM],  g_PHl[DD*MM];
__device__ __align__(16) bf16 g_XAh[MM*MM],  g_XAl[MM*MM];
__device__ __align__(16) bf16 g_XBh[MM*MM],  g_XBl[MM*MM];
__device__ __align__(16) bf16 g_XTh[MM*MM],  g_XTl[MM*MM];
__device__ __align__(16) bf16 g_TTh[MM*MM],  g_TTl[MM*MM];
__device__ __align__(16) bf16 g_Kh[DD*MM],   g_Kl[DD*MM];

// ---------------- split helpers ---------------------------------------------
__device__ __forceinline__ void hl(float v, bf16& h, bf16& l) {
    h = __float2bfloat16_rn(v);
    l = __float2bfloat16_rn(v - __bfloat162float(h));
}

__global__ void split_kernel(const float4* __restrict__ in,
                             bf16* __restrict__ hi, bf16* __restrict__ lo, int n4)
{
    int i = blockIdx.x * blockDim.x + threadIdx.x;
    if (i >= n4) return;
    float4 v = in[i];
    bf16 h0,h1,h2,h3,l0,l1,l2,l3;
    hl(v.x,h0,l0); hl(v.y,h1,l1); hl(v.z,h2,l2); hl(v.w,h3,l3);
    ((__nv_bfloat162*)hi)[2*i+0] = __nv_bfloat162(h0,h1);
    ((__nv_bfloat162*)hi)[2*i+1] = __nv_bfloat162(h2,h3);
    ((__nv_bfloat162*)lo)[2*i+0] = __nv_bfloat162(l0,l1);
    ((__nv_bfloat162*)lo)[2*i+1] = __nv_bfloat162(l2,l3);
}

// transpose-split: src [R,C] -> planes [C,R]
__global__ void splitT_kernel(const float* __restrict__ in,
                              bf16* __restrict__ hi, bf16* __restrict__ lo,
                              int R, int C)
{
    __shared__ float t[32][33];
    const int r0 = blockIdx.y * 32, c0 = blockIdx.x * 32;
    const int tx = threadIdx.x, ty = threadIdx.y;  // 32 x 8
#pragma unroll
    for (int i = 0; i < 32; i += 8)
        t[ty + i][tx] = in[(size_t)(r0 + ty + i) * C + c0 + tx];
    __syncthreads();
#pragma unroll
    for (int i = 0; i < 32; i += 8) {
        bf16 h, l; hl(t[tx][ty + i], h, l);
        size_t o = (size_t)(c0 + ty + i) * R + r0 + tx;
        hi[o] = h; lo[o] = l;
    }
}

// ======================= double-buffered plane GEMM (R15 winner) ============
__device__ __forceinline__ void mma16816(float c[4], const uint32_t a[4],
                                         uint32_t b0, uint32_t b1) {
    asm volatile("mma.sync.aligned.m16n8k16.row.col.f32.bf16.bf16.f32 "
                 "{%0,%1,%2,%3}, {%4,%5,%6,%7}, {%8,%9}, {%0,%1,%2,%3};"
                 : "+f"(c[0]), "+f"(c[1]), "+f"(c[2]), "+f"(c[3])
                 : "r"(a[0]), "r"(a[1]), "r"(a[2]), "r"(a[3]), "r"(b0), "r"(b1));
}
__device__ __forceinline__ void store_hl2(bf16* hi, bf16* lo, size_t off, float2 v) {
    bf16 h0,l0,h1,l1; hl(v.x,h0,l0); hl(v.y,h1,l1);
    *(__nv_bfloat162*)(hi + off) = __nv_bfloat162(h0,h1);
    *(__nv_bfloat162*)(lo + off) = __nv_bfloat162(l0,l1);
}
__device__ __forceinline__ void store_hlT(bf16* th, bf16* tl, int Mdim,
                                          int row, int col, float2 v) {
    bf16 h, l;
    hl(v.x, h, l);
    th[(size_t)col * Mdim + row] = h; tl[(size_t)col * Mdim + row] = l;
    hl(v.y, h, l);
    th[(size_t)(col + 1) * Mdim + row] = h; tl[(size_t)(col + 1) * Mdim + row] = l;
}

template <int BM, bool FULL>
__global__ __launch_bounds__(2 * BM)
void pgemm(int M, int N, int K,
           const bf16* __restrict__ Ah, const bf16* __restrict__ Al,
           const bf16* __restrict__ Bh, const bf16* __restrict__ Bl,
           const float* __restrict__ Cin, float* __restrict__ Cout,
           float alpha, float beta,
           bf16* __restrict__ Ph, bf16* __restrict__ Pl,
           bf16* __restrict__ PTh, bf16* __restrict__ PTl)
{
    constexpr int SA = 24;
    constexpr int NG = BM / 16;
    __shared__ alignas(16) bf16 sAh[2][BM * SA];
    __shared__ alignas(16) bf16 sBh[2][BM * SA];
    __shared__ alignas(16) bf16 sAl[FULL ? 2 : 1][BM * SA];
    __shared__ alignas(16) bf16 sBl[FULL ? 2 : 1][BM * SA];

    const int tid = threadIdx.x;
    const int wid = tid / 32, lane = tid % 32;
    const int warpM = wid / 2, warpN = wid % 2;
    const int g = lane >> 2, t = lane & 3;
    const int bm = blockIdx.y * BM, bn = blockIdx.x * BM;

    const int arow = tid >> 1, acol = (tid & 1) * 8;

    uint4 rah, ral, rbh, rbl;
    auto ldg = [&](int k0) {
        rah = *(const uint4*)(Ah + (size_t)(bm + arow) * K + k0 + acol);
        rbh = *(const uint4*)(Bh + (size_t)(bn + arow) * K + k0 + acol);
        if (FULL) {
            ral = *(const uint4*)(Al + (size_t)(bm + arow) * K + k0 + acol);
            rbl = *(const uint4*)(Bl + (size_t)(bn + arow) * K + k0 + acol);
        }
    };
    auto sts = [&](int s) {
        *(uint4*)(&sAh[s][arow * SA + acol]) = rah;
        *(uint4*)(&sBh[s][arow * SA + acol]) = rbh;
        if (FULL) {
            *(uint4*)(&sAl[s][arow * SA + acol]) = ral;
            *(uint4*)(&sBl[s][arow * SA + acol]) = rbl;
        }
    };

    float acc[2][NG][4];
#pragma unroll
    for (int mt = 0; mt < 2; mt++)
#pragma unroll
        for (int nt = 0; nt < NG; nt++)
#pragma unroll
            for (int q = 0; q < 4; q++) acc[mt][nt][q] = 0.f;

    ldg(0); sts(0); __syncthreads();
    int s = 0;
    for (int k0 = 0; k0 < K; k0 += 16) {
        const bool hasNext = (k0 + 16 < K);
        if (hasNext) ldg(k0 + 16);

        uint32_t ah[2][4], al[2][4];
#pragma unroll
        for (int mt = 0; mt < 2; mt++) {
            const int r = warpM * 32 + mt * 16;
            ah[mt][0] = *(const uint32_t*)&sAh[s][(r + g) * SA + 2 * t];
            ah[mt][1] = *(const uint32_t*)&sAh[s][(r + g + 8) * SA + 2 * t];
            ah[mt][2] = *(const uint32_t*)&sAh[s][(r + g) * SA + 2 * t + 8];
            ah[mt][3] = *(const uint32_t*)&sAh[s][(r + g + 8) * SA + 2 * t + 8];
            if (FULL) {
                al[mt][0] = *(const uint32_t*)&sAl[s][(r + g) * SA + 2 * t];
                al[mt][1] = *(const uint32_t*)&sAl[s][(r + g + 8) * SA + 2 * t];
                al[mt][2] = *(const uint32_t*)&sAl[s][(r + g) * SA + 2 * t + 8];
                al[mt][3] = *(const uint32_t*)&sAl[s][(r + g + 8) * SA + 2 * t + 8];
            }
        }
#pragma unroll
        for (int ng = 0; ng < NG; ng++) {
            const int n = warpN * (BM / 2) + ng * 8 + g;
            uint32_t bh0 = *(const uint32_t*)&sBh[s][n * SA + 2 * t];
            uint32_t bh1 = *(const uint32_t*)&sBh[s][n * SA + 2 * t + 8];
            if (FULL) {
                uint32_t bl0 = *(const uint32_t*)&sBl[s][n * SA + 2 * t];
                uint32_t bl1 = *(const uint32_t*)&sBl[s][n * SA + 2 * t + 8];
#pragma unroll
                for (int mt = 0; mt < 2; mt++) {
                    mma16816(acc[mt][ng], ah[mt], bh0, bh1);
                    mma16816(acc[mt][ng], ah[mt], bl0, bl1);
                    mma16816(acc[mt][ng], al[mt], bh0, bh1);
                }
            } else {
#pragma unroll
                for (int mt = 0; mt < 2; mt++)
                    mma16816(acc[mt][ng], ah[mt], bh0, bh1);
            }
        }
        if (hasNext) { sts(s ^ 1); __syncthreads(); s ^= 1; }
    }

#pragma unroll
    for (int mt = 0; mt < 2; mt++) {
        const int rowb = bm + warpM * 32 + mt * 16;
#pragma unroll
        for (int nt = 0; nt < NG; nt++) {
            const int col = bn + warpN * (BM / 2) + nt * 8 + 2 * t;
            const int r0 = rowb + g, r1 = rowb + g + 8;
            float2 c01 = make_float2(alpha * acc[mt][nt][0], alpha * acc[mt][nt][1]);
            float2 c23 = make_float2(alpha * acc[mt][nt][2], alpha * acc[mt][nt][3]);
            if (beta != 0.f) {
                float2 p0 = *(const float2*)(Cin + (size_t)r0 * N + col);
                float2 p1 = *(const float2*)(Cin + (size_t)r1 * N + col);
                c01.x += beta * p0.x; c01.y += beta * p0.y;
                c23.x += beta * p1.x; c23.y += beta * p1.y;
            }
            *(float2*)(Cout + (size_t)r0 * N + col) = c01;
            *(float2*)(Cout + (size_t)r1 * N + col) = c23;
            if (Ph) {
                store_hl2(Ph, Pl, (size_t)r0 * N + col, c01);
                store_hl2(Ph, Pl, (size_t)r1 * N + col, c23);
            }
            if (PTh) {
                store_hlT(PTh, PTl, M, r0, col, c01);
                store_hlT(PTh, PTl, M, r1, col, c23);
            }
        }
    }
}

// ---------------- Newton-Schulz support -------------------------------------
__global__ void ones_kernel(float* v) { v[threadIdx.x] = 1.f; }  // 512 threads

// y = S x  (trans=0) or y = S^T x (trans=1); one warp per row.
__global__ void matvec_kernel(const float* __restrict__ S,
                              const float* __restrict__ x,
                              float* __restrict__ y, int trans)
{
    const int row = blockIdx.x * 4 + (threadIdx.x >> 5);
    const int lane = threadIdx.x & 31;
    float sum = 0.f;
    if (trans) {
        for (int j = lane; j < MM; j += 32) sum += S[(size_t)j * MM + row] * x[j];
    } else {
        for (int j = lane; j < MM; j += 32) sum += S[(size_t)row * MM + j] * x[j];
    }
#pragma unroll
    for (int o = 16; o; o >>= 1) sum += __shfl_xor_sync(0xffffffffu, sum, o);
    if (lane == 0) y[row] = sum;
}

// norms[0] = ||a||^2, norms[1] = ||b||^2  (512 threads, one block)
__global__ void vnorms_kernel(const float* __restrict__ a,
                              const float* __restrict__ b, float* norms)
{
    __shared__ float sa[512], sb[512];
    const int i = threadIdx.x;
    sa[i] = a[i] * a[i];
    sb[i] = b[i] * b[i];
    __syncthreads();
    for (int o = 256; o > 0; o >>= 1) {
        if (i < o) { sa[i] += sa[i + o]; sb[i] += sb[i + o]; }
        __syncthreads();
    }
    if (i == 0) { norms[0] = sa[0]; norms[1] = sb[0]; }
}

// X0 = a * S^T with a = 0.98 * sqrt(norms[0]/norms[1]) = 0.98/lambda_est
__global__ void init_X_kernel(const float* __restrict__ S,
                              const float* __restrict__ norms,
                              float* __restrict__ X,
                              bf16* __restrict__ Xh, bf16* __restrict__ Xl,
                              bf16* __restrict__ XTh, bf16* __restrict__ XTl) {
    const float scale = 0.98f * sqrtf(norms[0] / norms[1]);
    const int idx = blockIdx.x * blockDim.x + threadIdx.x;
    const int i = idx / MM, j = idx % MM;
    float v = S[(size_t)j * MM + i] * scale;
    X[idx] = v;
    bf16 h, l; hl(v, h, l);
    Xh[idx] = h; Xl[idx] = l;
    XTh[(size_t)j * MM + i] = h; XTl[(size_t)j * MM + i] = l;
}

// ---------------- host-side dispatch ----------------------------------------
#define SYM(p, s) cudaGetSymbolAddress((void**)&p, s)

static void pg(cudaStream_t st, int M, int N, int K,
               const bf16* Ah, const bf16* Al, const bf16* Bh, const bf16* Bl,
               const float* Cin, float* C, float alpha, float beta,
               bf16* Ph = nullptr, bf16* Pl = nullptr,
               bf16* PTh = nullptr, bf16* PTl = nullptr, bool full = true)
{
    if (N == BB) {
        dim3 grd(N / 128, M / 128);
        pgemm<128, true><<<grd, 256, 0, st>>>(M, N, K, Ah, Al, Bh, Bl, Cin, C,
                                              alpha, beta, Ph, Pl, PTh, PTl);
    } else {
        dim3 grd(N / 64, M / 64);
        if (full)
            pgemm<64, true><<<grd, 128, 0, st>>>(M, N, K, Ah, Al, Bh, Bl, Cin, C,
                                                 alpha, beta, Ph, Pl, PTh, PTl);
        else
            pgemm<64, false><<<grd, 128, 0, st>>>(M, N, K, Ah, Al, Bh, Bl, Cin, C,
                                                  alpha, beta, Ph, Pl, PTh, PTl);
    }
}
static void split(cudaStream_t st, const float* src, bf16* h, bf16* l, int n) {
    split_kernel<<<(n / 4 + 255) / 256, 256, 0, st>>>((const float4*)src, h, l, n / 4);
}
static void splitT(cudaStream_t st, const float* src, bf16* h, bf16* l, int R, int C) {
    splitT_kernel<<<dim3(C / 32, R / 32), dim3(32, 8), 0, st>>>(src, h, l, R, C);
}

extern "C" void kernel_launch(void* const* d_in, const int* in_sizes, int n_in,
                              void* d_out, int out_size)
{
    (void)in_sizes; (void)n_in; (void)out_size;
    const float* state     = (const float*)d_in[0];
    const float* state_cov = (const float*)d_in[1];
    const float* meas      = (const float*)d_in[2];
    const float* control   = (const float*)d_in[3];
    const float* F         = (const float*)d_in[4];
    const float* Q         = (const float*)d_in[5];
    const float* Bc        = (const float*)d_in[6];
    const float* H         = (const float*)d_in[7];
    const float* R         = (const float*)d_in[8];
    float* out_state = (float*)d_out;
    float* out_cov   = out_state + (size_t)DD * BB;

    float *sp,*fs,*cp,*innov,*hp,*S,*X,*X2,*T,*pht,*Kg,*pv,*norms;
    SYM(sp,g_sp); SYM(fs,g_fs); SYM(cp,g_cp); SYM(innov,g_innov); SYM(hp,g_hp);
    SYM(S,g_S); SYM(X,g_X); SYM(X2,g_X2); SYM(T,g_T); SYM(pht,g_pht);
    SYM(Kg,g_K); SYM(pv,g_pv); SYM(norms,g_norms);
    bf16 *Fh,*Fl,*Hh,*Hl,*Bch,*Bcl,*BTh,*BTl,*CTh,*CTl,*CtlTh,*CtlTl;
    bf16 *FSh,*FSl,*CPh,*CPl,*CPTh,*CPTl,*HPh,*HPl,*HPTh,*HPTl,*Sh,*Sl;
    bf16 *PHh,*PHl,*XAh,*XAl,*XBh,*XBl,*XTh,*XTl,*TTh,*TTl,*Kh,*Kl;
    SYM(Fh,g_Fh); SYM(Fl,g_Fl); SYM(Hh,g_Hh); SYM(Hl,g_Hl);
    SYM(Bch,g_Bch); SYM(Bcl,g_Bcl); SYM(BTh,g_BTh); SYM(BTl,g_BTl);
    SYM(CTh,g_CTh); SYM(CTl,g_CTl); SYM(CtlTh,g_CtlTh); SYM(CtlTl,g_CtlTl);
    SYM(FSh,g_FSh); SYM(FSl,g_FSl); SYM(CPh,g_CPh); SYM(CPl,g_CPl);
    SYM(CPTh,g_CPTh); SYM(CPTl,g_CPTl);
    SYM(HPh,g_HPh); SYM(HPl,g_HPl); SYM(HPTh,g_HPTh); SYM(HPTl,g_HPTl);
    SYM(Sh,g_Sh); SYM(Sl,g_Sl); SYM(PHh,g_PHh); SYM(PHl,g_PHl);
    SYM(XAh,g_XAh); SYM(XAl,g_XAl); SYM(XBh,g_XBh); SYM(XBl,g_XBl);
    SYM(XTh,g_XTh); SYM(XTl,g_XTl); SYM(TTh,g_TTh); SYM(TTl,g_TTl);
    SYM(Kh,g_Kh); SYM(Kl,g_Kl);

    cudaStream_t s2 = 0;
    cudaEvent_t evF = 0, evJ = 0, evK = 0, evC = 0;
    bool dual =
        (cudaStreamCreateWithFlags(&s2, cudaStreamNonBlocking) == cudaSuccess) &&
        (cudaEventCreateWithFlags(&evF, cudaEventDisableTiming) == cudaSuccess) &&
        (cudaEventCreateWithFlags(&evJ, cudaEventDisableTiming) == cudaSuccess) &&
        (cudaEventCreateWithFlags(&evK, cudaEventDisableTiming) == cudaSuccess) &&
        (cudaEventCreateWithFlags(&evC, cudaEventDisableTiming) == cudaSuccess);
    cudaStream_t sb = dual ? s2 : (cudaStream_t)0;
    cudaStream_t sm = 0;

    // ---- common splits (main) ----
    split(sm, F, Fh, Fl, DD * DD);
    split(sm, H, Hh, Hl, MM * DD);
    if (dual) { cudaEventRecord(evF, sm); cudaStreamWaitEvent(s2, evF, 0); }

    // ================= state chain (sb) =================
    split(sb, Bc, Bch, Bcl, DD * CC);
    splitT(sb, state, BTh, BTl, DD, BB);
    splitT(sb, control, CtlTh, CtlTl, CC, BB);
    pg(sb, DD, BB, DD, Fh, Fl, BTh, BTl, nullptr, sp, 1.f, 0.f);     // sp=F@state
    pg(sb, DD, BB, CC, Bch, Bcl, CtlTh, CtlTl, sp, sp, 1.f, 1.f);    // +Bc@ctl
    splitT(sb, sp, BTh, BTl, DD, BB);
    pg(sb, MM, BB, DD, Hh, Hl, BTh, BTl, meas, innov, -1.f, 1.f);    // innov
    splitT(sb, innov, BTh, BTl, MM, BB);                             // innov^T
    if (dual) cudaEventRecord(evJ, s2);                              // sb done

    // ================= cov chain (sm) ===================
    splitT(sm, state_cov, CTh, CTl, DD, DD);
    pg(sm, DD, DD, DD, Fh, Fl, CTh, CTl, nullptr, fs, 1.f, 0.f,
       FSh, FSl);                                                    // fs
    pg(sm, DD, DD, DD, FSh, FSl, Fh, Fl, Q, cp, 1.f, 1.f,
       CPh, CPl, CPTh, CPTl);                                        // cp
    pg(sm, MM, DD, DD, Hh, Hl, CPTh, CPTl, nullptr, hp, 1.f, 0.f,
       HPh, HPl, HPTh, HPTl);                                        // hp
    pg(sm, MM, MM, DD, HPh, HPl, Hh, Hl, R, S, 1.f, 1.f, Sh, Sl);    // S
    pg(sm, DD, MM, DD, CPh, CPl, Hh, Hl, nullptr, pht, 1.f, 0.f,
       PHh, PHl);                                                    // pht

    // ---- spectral init: lambda_est = ||(S^T S)^2 v|| / ||(S^T S) v|| ----
    float* v0 = pv;  float* v1 = pv + MM;  float* v2 = pv + 2 * MM;
    float* v3 = pv + 3 * MM;
    ones_kernel<<<1, MM, 0, sm>>>(v0);
    matvec_kernel<<<MM / 4, 128, 0, sm>>>(S, v0, v1, 0);   // v1 = S v0
    matvec_kernel<<<MM / 4, 128, 0, sm>>>(S, v1, v2, 1);   // v2 = S^T v1
    matvec_kernel<<<MM / 4, 128, 0, sm>>>(S, v2, v3, 0);   // v3 = S v2
    matvec_kernel<<<MM / 4, 128, 0, sm>>>(S, v3, v1, 1);   // v1 = (S^T S)^2 v0
    vnorms_kernel<<<1, MM, 0, sm>>>(v2, v1, norms);        // ||v2||^2, ||v1||^2
    init_X_kernel<<<(MM * MM) / 256, 256, 0, sm>>>(S, norms, X, XAh, XAl,
                                                   XTh, XTl);
    float* cur = X;  float* nxt = X2;
    bf16 *curAh = XAh, *curAl = XAl, *nxtAh = XBh, *nxtAl = XBl;
    for (int it = 0; it < NS_ITERS; ++it) {
        const bool full = (it >= NS_ITERS - NS_FULL);
        pg(sm, MM, MM, MM, Sh, Sl, XTh, XTl, nullptr, T, 1.f, 0.f,
           nullptr, nullptr, TTh, TTl, full);                        // T=S@X
        pg(sm, MM, MM, MM, curAh, curAl, TTh, TTl, cur, nxt, -1.f, 2.f,
           nxtAh, nxtAl, XTh, XTl, full);                            // X'
        float* tf = cur; cur = nxt; nxt = tf;
        bf16* th = curAh; curAh = nxtAh; nxtAh = th;
        bf16* tl = curAl; curAl = nxtAl; nxtAl = tl;
    }
    pg(sm, DD, MM, MM, PHh, PHl, XTh, XTl, nullptr, Kg, 1.f, 0.f,
       Kh, Kl);                                                      // Kg

    // ================= join + outputs ==================
    if (dual) {
        cudaEventRecord(evK, sm);            // Kg ready
        cudaStreamWaitEvent(s2, evK, 0);
        // cov_n on sb (no sb-data deps; overlaps state_n)
        pg(sb, DD, DD, MM, Kh, Kl, HPTh, HPTl, cp, out_cov, -1.f, 1.f);
        cudaEventRecord(evC, s2);
        cudaStreamWaitEvent(sm, evJ, 0);     // innov ready
        pg(sm, DD, BB, MM, Kh, Kl, BTh, BTl, sp, out_state, 1.f, 1.f);
        cudaStreamWaitEvent(sm, evC, 0);     // rejoin sb before capture end
    } else {
        pg(sm, DD, BB, MM, Kh, Kl, BTh, BTl, sp, out_state, 1.f, 1.f);
        pg(sm, DD, DD, MM, Kh, Kl, HPTh, HPTl, cp, out_cov, -1.f, 1.f);
    }
}